// round 2
// baseline (speedup 1.0000x reference)
#include <cuda_runtime.h>
#include <math.h>

#define BATCH 4
#define SEQ   4096
#define EMB   1024
#define HDIM  128

// scratch for projections (allocation-free: __device__ globals)
__device__ float g_Q[(size_t)BATCH * SEQ * HDIM];
__device__ float g_K[(size_t)BATCH * SEQ * HDIM];
__device__ float g_V[(size_t)BATCH * SEQ * HDIM];

// ---------------------------------------------------------------------------
// Projection GEMM: out[m][n] = sum_e x[m][e] * W[n][e]
// M = BATCH*SEQ = 16384, N = HDIM = 128, K = EMB = 1024
// Tile 128x128x16, 256 threads, 8x8 register blocking.
// blockIdx.y selects which of (Wk, Wq, Wv).
// ---------------------------------------------------------------------------
__global__ __launch_bounds__(256) void proj_kernel(
    const float* __restrict__ x,
    const float* __restrict__ Wk,
    const float* __restrict__ Wq,
    const float* __restrict__ Wv)
{
    __shared__ float Xs[16][132];   // [k][m], padded to break store conflicts
    __shared__ float Ws[16][132];   // [k][n]

    const int which = blockIdx.y;
    const float* W = (which == 0) ? Wk : (which == 1) ? Wq : Wv;
    float* out = (which == 0) ? g_K : (which == 1) ? g_Q : g_V;

    const int m0  = blockIdx.x * 128;
    const int tid = threadIdx.x;
    const int tx  = tid & 15;       // 0..15  (n groups of 8)
    const int ty  = tid >> 4;       // 0..15  (m groups of 8)

    float acc[8][8];
#pragma unroll
    for (int i = 0; i < 8; i++)
#pragma unroll
        for (int j = 0; j < 8; j++) acc[i][j] = 0.0f;

    for (int e0 = 0; e0 < EMB; e0 += 16) {
        __syncthreads();
        // load tiles (transposed into [k][row]) — global reads coalesced
#pragma unroll
        for (int i = 0; i < 8; i++) {
            int idx = tid + i * 256;        // 0..2047
            int k = idx & 15;
            int r = idx >> 4;               // 0..127
            Xs[k][r] = x[(size_t)(m0 + r) * EMB + e0 + k];
            Ws[k][r] = W[(size_t)r * EMB + e0 + k];
        }
        __syncthreads();

#pragma unroll
        for (int k = 0; k < 16; k++) {
            float a[8], bb[8];
            *(float4*)&a[0]  = *(const float4*)&Xs[k][ty * 8];
            *(float4*)&a[4]  = *(const float4*)&Xs[k][ty * 8 + 4];
            *(float4*)&bb[0] = *(const float4*)&Ws[k][tx * 8];
            *(float4*)&bb[4] = *(const float4*)&Ws[k][tx * 8 + 4];
#pragma unroll
            for (int i = 0; i < 8; i++)
#pragma unroll
                for (int j = 0; j < 8; j++)
                    acc[i][j] = fmaf(a[i], bb[j], acc[i][j]);
        }
    }

    // write 8x8 tile
#pragma unroll
    for (int i = 0; i < 8; i++) {
        size_t row = (size_t)(m0 + ty * 8 + i) * HDIM + tx * 8;
        *(float4*)&out[row]     = make_float4(acc[i][0], acc[i][1], acc[i][2], acc[i][3]);
        *(float4*)&out[row + 4] = make_float4(acc[i][4], acc[i][5], acc[i][6], acc[i][7]);
    }
}

// ---------------------------------------------------------------------------
// Flash attention (causal), BQ=64 query rows, BK=64 key rows per iteration.
// 256 threads: thread (ty,tx) with tx=tid%16, ty=tid/16 owns
//   S sub-tile rows 4*ty..+4, cols 4*tx..+4 ; O sub-tile rows 4*ty..+4, cols 8*tx..+8
// Work pairing: block with pair index p handles q-tiles p and 63-p
// -> every block does exactly 65 key-tile iterations (perfect balance).
// ---------------------------------------------------------------------------
#define QK_PAD 68   // row stride (floats) for transposed Q/K tiles

extern __shared__ float smem_attn[];

__global__ __launch_bounds__(256) void attn_kernel(
    const float* __restrict__ Q,
    const float* __restrict__ K,
    const float* __restrict__ V,
    float* __restrict__ out)
{
    float* Qt = smem_attn;                  // [128][QK_PAD]  Qt[d*QK_PAD + r]
    float* Kt = Qt + 128 * QK_PAD;          // [128][QK_PAD]
    float* Vs = Kt + 128 * QK_PAD;          // [64][128] row-major
    float* Ps = Vs + 64 * 128;              // [64][64]

    const int b    = blockIdx.y;
    const int pair = blockIdx.x;            // 0..31
    const int tid  = threadIdx.x;
    const int tx   = tid & 15;
    const int ty   = tid >> 4;

    const size_t base = (size_t)b * SEQ * HDIM;
    const float* Qb = Q + base;
    const float* Kb = K + base;
    const float* Vb = V + base;

    for (int half = 0; half < 2; half++) {
        const int qt = (half == 0) ? pair : (63 - pair);

        __syncthreads();
        // load Q tile transposed, pre-scaled by EMB^-0.5 = 1/32
#pragma unroll
        for (int i = 0; i < 32; i++) {
            int idx = tid + i * 256;        // 0..8191
            int d = idx & 127;
            int r = idx >> 7;
            Qt[d * QK_PAD + r] = Qb[(size_t)(qt * 64 + r) * HDIM + d] * 0.03125f;
        }

        float o[4][8];
        float m_i[4], l_i[4];
#pragma unroll
        for (int i = 0; i < 4; i++) {
            m_i[i] = -INFINITY;
            l_i[i] = 0.0f;
#pragma unroll
            for (int c = 0; c < 8; c++) o[i][c] = 0.0f;
        }

        for (int kt = 0; kt <= qt; kt++) {
            __syncthreads();   // previous PV / Q-load complete before overwrite
            // load K tile transposed
#pragma unroll
            for (int i = 0; i < 32; i++) {
                int idx = tid + i * 256;
                int d = idx & 127;
                int r = idx >> 7;
                Kt[d * QK_PAD + r] = Kb[(size_t)(kt * 64 + r) * HDIM + d];
            }
            // load V tile row-major (float4 copy)
            const float4* vsrc = (const float4*)(Vb + (size_t)(kt * 64) * HDIM);
            float4* vdst = (float4*)Vs;
#pragma unroll
            for (int i = 0; i < 8; i++) {
                int idx4 = tid + i * 256;   // 0..2047
                vdst[idx4] = vsrc[idx4];
            }
            __syncthreads();

            // ---- S = Q K^T (64x64), this thread: 4x4 ----
            float s[4][4];
#pragma unroll
            for (int i = 0; i < 4; i++)
#pragma unroll
                for (int j = 0; j < 4; j++) s[i][j] = 0.0f;

            const float* qbase = Qt + ty * 4;
            const float* kbase = Kt + tx * 4;
#pragma unroll 8
            for (int d = 0; d < 128; d++) {
                float4 a  = *(const float4*)(qbase + d * QK_PAD);
                float4 bb = *(const float4*)(kbase + d * QK_PAD);
                s[0][0] = fmaf(a.x, bb.x, s[0][0]); s[0][1] = fmaf(a.x, bb.y, s[0][1]);
                s[0][2] = fmaf(a.x, bb.z, s[0][2]); s[0][3] = fmaf(a.x, bb.w, s[0][3]);
                s[1][0] = fmaf(a.y, bb.x, s[1][0]); s[1][1] = fmaf(a.y, bb.y, s[1][1]);
                s[1][2] = fmaf(a.y, bb.z, s[1][2]); s[1][3] = fmaf(a.y, bb.w, s[1][3]);
                s[2][0] = fmaf(a.z, bb.x, s[2][0]); s[2][1] = fmaf(a.z, bb.y, s[2][1]);
                s[2][2] = fmaf(a.z, bb.z, s[2][2]); s[2][3] = fmaf(a.z, bb.w, s[2][3]);
                s[3][0] = fmaf(a.w, bb.x, s[3][0]); s[3][1] = fmaf(a.w, bb.y, s[3][1]);
                s[3][2] = fmaf(a.w, bb.z, s[3][2]); s[3][3] = fmaf(a.w, bb.w, s[3][3]);
            }

            // causal mask on the diagonal tile
            if (kt == qt) {
#pragma unroll
                for (int i = 0; i < 4; i++)
#pragma unroll
                    for (int j = 0; j < 4; j++)
                        if (4 * tx + j > 4 * ty + i) s[i][j] = -INFINITY;
            }

            // ---- online softmax ----
            float rmax[4];
#pragma unroll
            for (int i = 0; i < 4; i++) {
                rmax[i] = fmaxf(fmaxf(s[i][0], s[i][1]), fmaxf(s[i][2], s[i][3]));
            }
#pragma unroll
            for (int off = 8; off >= 1; off >>= 1)
#pragma unroll
                for (int i = 0; i < 4; i++)
                    rmax[i] = fmaxf(rmax[i], __shfl_xor_sync(0xffffffffu, rmax[i], off));

            float alpha[4], rsum[4];
#pragma unroll
            for (int i = 0; i < 4; i++) {
                float mnew = fmaxf(m_i[i], rmax[i]);
                alpha[i] = __expf(m_i[i] - mnew);   // exp(-inf)=0 on first tile
                m_i[i] = mnew;
                float p0 = __expf(s[i][0] - mnew);
                float p1 = __expf(s[i][1] - mnew);
                float p2 = __expf(s[i][2] - mnew);
                float p3 = __expf(s[i][3] - mnew);
                rsum[i] = (p0 + p1) + (p2 + p3);
                *(float4*)&Ps[(4 * ty + i) * 64 + 4 * tx] = make_float4(p0, p1, p2, p3);
            }
#pragma unroll
            for (int off = 8; off >= 1; off >>= 1)
#pragma unroll
                for (int i = 0; i < 4; i++)
                    rsum[i] += __shfl_xor_sync(0xffffffffu, rsum[i], off);
#pragma unroll
            for (int i = 0; i < 4; i++) {
                l_i[i] = l_i[i] * alpha[i] + rsum[i];
#pragma unroll
                for (int c = 0; c < 8; c++) o[i][c] *= alpha[i];
            }
            __syncthreads();   // Ps visible to all

            // ---- O += P V ----
            const float* pbase = Ps + ty * 4 * 64;
            const float* vbase = Vs + tx * 8;
#pragma unroll 4
            for (int j = 0; j < 64; j++) {
                float p0 = pbase[j];
                float p1 = pbase[64 + j];
                float p2 = pbase[128 + j];
                float p3 = pbase[192 + j];
                float4 v0 = *(const float4*)(vbase + j * 128);
                float4 v1 = *(const float4*)(vbase + j * 128 + 4);
                o[0][0] = fmaf(p0, v0.x, o[0][0]); o[0][1] = fmaf(p0, v0.y, o[0][1]);
                o[0][2] = fmaf(p0, v0.z, o[0][2]); o[0][3] = fmaf(p0, v0.w, o[0][3]);
                o[0][4] = fmaf(p0, v1.x, o[0][4]); o[0][5] = fmaf(p0, v1.y, o[0][5]);
                o[0][6] = fmaf(p0, v1.z, o[0][6]); o[0][7] = fmaf(p0, v1.w, o[0][7]);
                o[1][0] = fmaf(p1, v0.x, o[1][0]); o[1][1] = fmaf(p1, v0.y, o[1][1]);
                o[1][2] = fmaf(p1, v0.z, o[1][2]); o[1][3] = fmaf(p1, v0.w, o[1][3]);
                o[1][4] = fmaf(p1, v1.x, o[1][4]); o[1][5] = fmaf(p1, v1.y, o[1][5]);
                o[1][6] = fmaf(p1, v1.z, o[1][6]); o[1][7] = fmaf(p1, v1.w, o[1][7]);
                o[2][0] = fmaf(p2, v0.x, o[2][0]); o[2][1] = fmaf(p2, v0.y, o[2][1]);
                o[2][2] = fmaf(p2, v0.z, o[2][2]); o[2][3] = fmaf(p2, v0.w, o[2][3]);
                o[2][4] = fmaf(p2, v1.x, o[2][4]); o[2][5] = fmaf(p2, v1.y, o[2][5]);
                o[2][6] = fmaf(p2, v1.z, o[2][6]); o[2][7] = fmaf(p2, v1.w, o[2][7]);
                o[3][0] = fmaf(p3, v0.x, o[3][0]); o[3][1] = fmaf(p3, v0.y, o[3][1]);
                o[3][2] = fmaf(p3, v0.z, o[3][2]); o[3][3] = fmaf(p3, v0.w, o[3][3]);
                o[3][4] = fmaf(p3, v1.x, o[3][4]); o[3][5] = fmaf(p3, v1.y, o[3][5]);
                o[3][6] = fmaf(p3, v1.z, o[3][6]); o[3][7] = fmaf(p3, v1.w, o[3][7]);
            }
        }

        // ---- epilogue: O / l, write out ----
#pragma unroll
        for (int i = 0; i < 4; i++) {
            float inv = 1.0f / l_i[i];
            size_t row = base + (size_t)(qt * 64 + 4 * ty + i) * HDIM + tx * 8;
            *(float4*)&out[row]     = make_float4(o[i][0] * inv, o[i][1] * inv,
                                                  o[i][2] * inv, o[i][3] * inv);
            *(float4*)&out[row + 4] = make_float4(o[i][4] * inv, o[i][5] * inv,
                                                  o[i][6] * inv, o[i][7] * inv);
        }
    }
}

// ---------------------------------------------------------------------------
extern "C" void kernel_launch(void* const* d_in, const int* in_sizes, int n_in,
                              void* d_out, int out_size)
{
    const float* x  = (const float*)d_in[0];
    const float* Wk = (const float*)d_in[1];
    const float* Wq = (const float*)d_in[2];
    const float* Wv = (const float*)d_in[3];
    float* out = (float*)d_out;

    // projections: 128 M-tiles x 3 weights
    proj_kernel<<<dim3(128, 3), 256>>>(x, Wk, Wq, Wv);

    // resolve device-global scratch addresses (host API, capture-safe)
    static float *pQ = nullptr, *pK = nullptr, *pV = nullptr;
    if (!pQ) {
        cudaGetSymbolAddress((void**)&pQ, g_Q);
        cudaGetSymbolAddress((void**)&pK, g_K);
        cudaGetSymbolAddress((void**)&pV, g_V);
    }

    const size_t smem_bytes = (size_t)(128 * QK_PAD * 2 + 64 * 128 + 64 * 64) * sizeof(float);
    static bool attr_set = false;
    if (!attr_set) {
        cudaFuncSetAttribute(attn_kernel, cudaFuncAttributeMaxDynamicSharedMemorySize,
                             (int)smem_bytes);
        attr_set = true;
    }

    attn_kernel<<<dim3(32, BATCH), 256, smem_bytes>>>(pQ, pK, pV, out);
}

// round 4
// speedup vs baseline: 3.4842x; 3.4842x over previous
#include <cuda_runtime.h>
#include <cuda_bf16.h>
#include <math.h>
#include <cstdint>

#define BATCH 4
#define SEQ   4096
#define EMB   1024
#define HDIM  128

// ---------------------------------------------------------------------------
// scratch (allocation-free: __device__ globals) — all bf16 hi/lo split pairs
// ---------------------------------------------------------------------------
__device__ __nv_bfloat16 g_Qhi[(size_t)BATCH * SEQ * HDIM];
__device__ __nv_bfloat16 g_Qlo[(size_t)BATCH * SEQ * HDIM];
__device__ __nv_bfloat16 g_Khi[(size_t)BATCH * SEQ * HDIM];
__device__ __nv_bfloat16 g_Klo[(size_t)BATCH * SEQ * HDIM];
__device__ __nv_bfloat16 g_Vhi[(size_t)BATCH * SEQ * HDIM];
__device__ __nv_bfloat16 g_Vlo[(size_t)BATCH * SEQ * HDIM];
// split weights: [which][HDIM][EMB], which: 0=K,1=Q,2=V
__device__ __nv_bfloat16 g_Whi[3 * HDIM * EMB];
__device__ __nv_bfloat16 g_Wlo[3 * HDIM * EMB];

// ===========================================================================
// mma.sync / ldmatrix / cp.async helpers (baseline PTX, no 'a' features)
// ===========================================================================
__device__ __forceinline__ uint32_t smem_to_u32(const void* p) {
    uint32_t a;
    asm("{ .reg .u64 t; cvta.to.shared.u64 t, %1; cvt.u32.u64 %0, t; }"
        : "=r"(a) : "l"(p));
    return a;
}

__device__ __forceinline__ void ldsm_x4(uint32_t addr,
    uint32_t& r0, uint32_t& r1, uint32_t& r2, uint32_t& r3) {
    asm volatile("ldmatrix.sync.aligned.m8n8.x4.shared.b16 {%0,%1,%2,%3}, [%4];"
        : "=r"(r0), "=r"(r1), "=r"(r2), "=r"(r3) : "r"(addr));
}

__device__ __forceinline__ void ldsm_x4_t(uint32_t addr,
    uint32_t& r0, uint32_t& r1, uint32_t& r2, uint32_t& r3) {
    asm volatile("ldmatrix.sync.aligned.m8n8.x4.trans.shared.b16 {%0,%1,%2,%3}, [%4];"
        : "=r"(r0), "=r"(r1), "=r"(r2), "=r"(r3) : "r"(addr));
}

__device__ __forceinline__ void mma_bf16(float& c0, float& c1, float& c2, float& c3,
    uint32_t a0, uint32_t a1, uint32_t a2, uint32_t a3, uint32_t b0, uint32_t b1) {
    asm volatile(
        "mma.sync.aligned.m16n8k16.row.col.f32.bf16.bf16.f32 "
        "{%0,%1,%2,%3}, {%4,%5,%6,%7}, {%8,%9}, {%0,%1,%2,%3};"
        : "+f"(c0), "+f"(c1), "+f"(c2), "+f"(c3)
        : "r"(a0), "r"(a1), "r"(a2), "r"(a3), "r"(b0), "r"(b1));
}

#define CP_ASYNC16(dst, src) \
    asm volatile("cp.async.cg.shared.global [%0], [%1], 16;" :: "r"(dst), "l"(src))
#define CP_COMMIT()  asm volatile("cp.async.commit_group;" ::: "memory")
#define CP_WAIT0()   asm volatile("cp.async.wait_group 0;" ::: "memory")

// pack two floats into bf16x2 hi + residual lo
__device__ __forceinline__ void split2(float x0, float x1, uint32_t& hi, uint32_t& lo) {
    __nv_bfloat16 h0 = __float2bfloat16(x0);
    __nv_bfloat16 h1 = __float2bfloat16(x1);
    __nv_bfloat16 g0 = __float2bfloat16(x0 - __bfloat162float(h0));
    __nv_bfloat16 g1 = __float2bfloat16(x1 - __bfloat162float(h1));
    hi = (uint32_t)__bfloat16_as_ushort(h0) | ((uint32_t)__bfloat16_as_ushort(h1) << 16);
    lo = (uint32_t)__bfloat16_as_ushort(g0) | ((uint32_t)__bfloat16_as_ushort(g1) << 16);
}

// ===========================================================================
// Weight split prepass: W (fp32) -> (hi, lo) bf16
// ===========================================================================
__global__ __launch_bounds__(256) void wsplit_kernel(
    const float* __restrict__ Wk,
    const float* __restrict__ Wq,
    const float* __restrict__ Wv)
{
    int idx = blockIdx.x * 256 + threadIdx.x;
    if (idx >= 3 * HDIM * EMB) return;
    int which = idx >> 17;
    int within = idx & ((HDIM * EMB) - 1);
    const float* W = (which == 0) ? Wk : (which == 1) ? Wq : Wv;
    float w = W[within];
    __nv_bfloat16 hi = __float2bfloat16(w);
    __nv_bfloat16 lo = __float2bfloat16(w - __bfloat162float(hi));
    g_Whi[idx] = hi;
    g_Wlo[idx] = lo;
}

// ===========================================================================
// Projection GEMM via mma.sync bf16-split.
// grid (128 m-tiles, 3 heads), 256 threads (8 warps x 16 rows = 128 rows).
// out[m][n] = sum_e x[m][e]*W[n][e]; epilogue writes split bf16 (Q scaled).
// ===========================================================================
#define PR_ROWB 144               // 64 bf16 = 128B + 16B pad
#define PR_AHI  0
#define PR_ALO  18432             // 128*144
#define PR_BHI  36864
#define PR_BLO  55296
#define PR_SMEM 73728

extern __shared__ char dsmem[];

__global__ __launch_bounds__(256) void proj_mma_kernel(const float* __restrict__ x)
{
    char* smem = dsmem;
    uint32_t sb = smem_to_u32(smem);
    const int tid  = threadIdx.x;
    const int lane = tid & 31;
    const int w    = tid >> 5;
    const int m0   = blockIdx.x * 128;
    const int which = blockIdx.y;

    // ldmatrix lane offsets
    const uint32_t a_off = (uint32_t)(w * 16 + (lane & 15)) * PR_ROWB
                         + (uint32_t)((lane >> 4) << 3) * 2;
    const uint32_t b_off = (uint32_t)((lane & 7) + ((lane >> 4) << 3)) * PR_ROWB
                         + (uint32_t)(((lane >> 3) & 1) << 3) * 2;

    float o[16][4];
#pragma unroll
    for (int t = 0; t < 16; t++)
#pragma unroll
        for (int k = 0; k < 4; k++) o[t][k] = 0.0f;

    const int a_row  = tid >> 1;
    const int a_half = tid & 1;

    for (int e0 = 0; e0 < EMB; e0 += 64) {
        __syncthreads();
        // ---- A: load x fp32, split to bf16 hi/lo ----
        {
            const float* xr = x + (size_t)(m0 + a_row) * EMB + e0 + a_half * 32;
            uint32_t abase = (uint32_t)a_row * PR_ROWB + (uint32_t)(a_half * 32) * 2;
#pragma unroll
            for (int i = 0; i < 8; i++) {
                float4 v = *(const float4*)(xr + i * 4);
                uint32_t h01, l01, h23, l23;
                split2(v.x, v.y, h01, l01);
                split2(v.z, v.w, h23, l23);
                uint32_t off = abase + (uint32_t)(i * 4) * 2;
                *(uint32_t*)(smem + PR_AHI + off)     = h01;
                *(uint32_t*)(smem + PR_AHI + off + 4) = h23;
                *(uint32_t*)(smem + PR_ALO + off)     = l01;
                *(uint32_t*)(smem + PR_ALO + off + 4) = l23;
            }
        }
        // ---- B: copy pre-split W tiles ----
#pragma unroll
        for (int j = 0; j < 4; j++) {
            int idx = tid + j * 256;          // 0..1023
            int row = idx >> 3, c8 = idx & 7;
            size_t gsrc = (size_t)(which * HDIM + row) * EMB + e0 + c8 * 8;
            uint32_t doff = (uint32_t)row * PR_ROWB + (uint32_t)c8 * 16;
            *(uint4*)(smem + PR_BHI + doff) = *(const uint4*)(g_Whi + gsrc);
            *(uint4*)(smem + PR_BLO + doff) = *(const uint4*)(g_Wlo + gsrc);
        }
        __syncthreads();

        // ---- MMA ----
#pragma unroll
        for (int kk = 0; kk < 4; kk++) {
            uint32_t ah0, ah1, ah2, ah3, al0, al1, al2, al3;
            ldsm_x4(sb + PR_AHI + a_off + kk * 32, ah0, ah1, ah2, ah3);
            ldsm_x4(sb + PR_ALO + a_off + kk * 32, al0, al1, al2, al3);
#pragma unroll
            for (int np = 0; np < 8; np++) {
                uint32_t bh0, bh1, bh2, bh3, bl0, bl1, bl2, bl3;
                uint32_t boff = b_off + (uint32_t)(np * 16) * PR_ROWB + kk * 32;
                ldsm_x4(sb + PR_BHI + boff, bh0, bh1, bh2, bh3);
                ldsm_x4(sb + PR_BLO + boff, bl0, bl1, bl2, bl3);
                int t0 = 2 * np, t1 = t0 + 1;
                mma_bf16(o[t0][0], o[t0][1], o[t0][2], o[t0][3], ah0, ah1, ah2, ah3, bh0, bh1);
                mma_bf16(o[t0][0], o[t0][1], o[t0][2], o[t0][3], ah0, ah1, ah2, ah3, bl0, bl1);
                mma_bf16(o[t0][0], o[t0][1], o[t0][2], o[t0][3], al0, al1, al2, al3, bh0, bh1);
                mma_bf16(o[t1][0], o[t1][1], o[t1][2], o[t1][3], ah0, ah1, ah2, ah3, bh2, bh3);
                mma_bf16(o[t1][0], o[t1][1], o[t1][2], o[t1][3], ah0, ah1, ah2, ah3, bl2, bl3);
                mma_bf16(o[t1][0], o[t1][1], o[t1][2], o[t1][3], al0, al1, al2, al3, bh2, bh3);
            }
        }
    }

    // ---- epilogue: split result, write bf16 hi/lo; Q scaled by 1/32 ----
    const float scale = (which == 1) ? 0.03125f : 1.0f;
    __nv_bfloat16* dh = (which == 0) ? g_Khi : (which == 1) ? g_Qhi : g_Vhi;
    __nv_bfloat16* dl = (which == 0) ? g_Klo : (which == 1) ? g_Qlo : g_Vlo;
    const int r0 = m0 + w * 16 + (lane >> 2);
    const int r1 = r0 + 8;
#pragma unroll
    for (int nt = 0; nt < 16; nt++) {
        int col = nt * 8 + 2 * (lane & 3);
        uint32_t hi, lo;
        split2(o[nt][0] * scale, o[nt][1] * scale, hi, lo);
        *(uint32_t*)(dh + (size_t)r0 * HDIM + col) = hi;
        *(uint32_t*)(dl + (size_t)r0 * HDIM + col) = lo;
        split2(o[nt][2] * scale, o[nt][3] * scale, hi, lo);
        *(uint32_t*)(dh + (size_t)r1 * HDIM + col) = hi;
        *(uint32_t*)(dl + (size_t)r1 * HDIM + col) = lo;
    }
}

// ===========================================================================
// Flash attention via mma.sync bf16-split.
// grid (32 pairs, 4 batch), 128 threads (4 warps x 16 query rows, BQ=64, BK=64).
// Pair (p, 63-p): 65 balanced K-iterations. Double-buffered K/V via cp.async.
// ===========================================================================
#define AT_ROWB 272               // 128 bf16 = 256B + 16B pad
#define AT_TILE 17408             // 64*272
#define AT_QHI  0
#define AT_QLO  17408
#define AT_KV   34816             // + buf*69632 : KHI,KLO,VHI,VLO
#define AT_BUF  69632
#define AT_SMEM 174080

__device__ __forceinline__ void prefetch_kv(uint32_t sb_buf, int grow, int tid)
{
#pragma unroll
    for (int t = 0; t < 4; t++) {
        const __nv_bfloat16* g =
            (t == 0) ? g_Khi : (t == 1) ? g_Klo : (t == 2) ? g_Vhi : g_Vlo;
        g += (size_t)grow * HDIM;
        uint32_t tb = sb_buf + t * AT_TILE;
#pragma unroll
        for (int j = 0; j < 8; j++) {
            int idx = tid + j * 128;
            int row = idx >> 4, c16 = idx & 15;
            uint32_t dst = tb + (uint32_t)row * AT_ROWB + (uint32_t)c16 * 16;
            CP_ASYNC16(dst, (const void*)(g + (size_t)row * HDIM + c16 * 8));
        }
    }
    CP_COMMIT();
}

__global__ __launch_bounds__(128) void attn_mma_kernel(float* __restrict__ out)
{
    char* smem = dsmem;
    uint32_t sb = smem_to_u32(smem);
    const int tid  = threadIdx.x;
    const int lane = tid & 31;
    const int w    = tid >> 5;
    const int b    = blockIdx.y;
    const int pair = blockIdx.x;
    const int bbase = b * SEQ;

    // ldmatrix lane offsets
    const uint32_t a_off = (uint32_t)(w * 16 + (lane & 15)) * AT_ROWB
                         + (uint32_t)((lane >> 4) << 3) * 2;
    const uint32_t b_off = (uint32_t)((lane & 7) + ((lane >> 4) << 3)) * AT_ROWB
                         + (uint32_t)(((lane >> 3) & 1) << 3) * 2;
    const uint32_t v_off = (uint32_t)((lane & 7) + (((lane >> 3) & 1) << 3)) * AT_ROWB
                         + (uint32_t)((lane >> 4) << 3) * 2;

    for (int half = 0; half < 2; half++) {
        const int qt = half ? (63 - pair) : pair;
        const int nkt = qt + 1;

        // ---- stage Q tile (hi/lo) into smem ----
        __syncthreads();
        {
            const size_t gq = (size_t)(bbase + qt * 64) * HDIM;
#pragma unroll
            for (int j = 0; j < 8; j++) {
                int idx = tid + j * 128;
                int row = idx >> 4, c16 = idx & 15;
                uint32_t doff = (uint32_t)row * AT_ROWB + (uint32_t)c16 * 16;
                *(uint4*)(smem + AT_QHI + doff) =
                    *(const uint4*)(g_Qhi + gq + (size_t)row * HDIM + c16 * 8);
                *(uint4*)(smem + AT_QLO + doff) =
                    *(const uint4*)(g_Qlo + gq + (size_t)row * HDIM + c16 * 8);
            }
        }
        __syncthreads();

        float o[16][4];
#pragma unroll
        for (int t = 0; t < 16; t++)
#pragma unroll
            for (int k = 0; k < 4; k++) o[t][k] = 0.0f;
        float m0 = -INFINITY, m1 = -INFINITY, l0 = 0.0f, l1 = 0.0f;

        prefetch_kv(sb + AT_KV, bbase, tid);   // kt = 0 into buf 0

        for (int kt = 0; kt < nkt; kt++) {
            CP_WAIT0();
            __syncthreads();
            if (kt + 1 < nkt)
                prefetch_kv(sb + AT_KV + ((kt + 1) & 1) * AT_BUF,
                            bbase + (kt + 1) * 64, tid);
            const uint32_t kb = sb + AT_KV + (kt & 1) * AT_BUF;

            // ---- S = Q K^T (3-product split) ----
            float s[8][4];
#pragma unroll
            for (int t = 0; t < 8; t++)
#pragma unroll
                for (int k = 0; k < 4; k++) s[t][k] = 0.0f;

#pragma unroll
            for (int kk = 0; kk < 8; kk++) {
                uint32_t qh0, qh1, qh2, qh3, ql0, ql1, ql2, ql3;
                ldsm_x4(sb + AT_QHI + a_off + kk * 32, qh0, qh1, qh2, qh3);
                ldsm_x4(sb + AT_QLO + a_off + kk * 32, ql0, ql1, ql2, ql3);
#pragma unroll
                for (int np = 0; np < 4; np++) {
                    uint32_t kh0, kh1, kh2, kh3, kl0, kl1, kl2, kl3;
                    uint32_t boff = b_off + (uint32_t)(np * 16) * AT_ROWB + kk * 32;
                    ldsm_x4(kb + 0 * AT_TILE + boff, kh0, kh1, kh2, kh3);
                    ldsm_x4(kb + 1 * AT_TILE + boff, kl0, kl1, kl2, kl3);
                    int t0 = 2 * np, t1 = t0 + 1;
                    mma_bf16(s[t0][0], s[t0][1], s[t0][2], s[t0][3], qh0, qh1, qh2, qh3, kh0, kh1);
                    mma_bf16(s[t0][0], s[t0][1], s[t0][2], s[t0][3], qh0, qh1, qh2, qh3, kl0, kl1);
                    mma_bf16(s[t0][0], s[t0][1], s[t0][2], s[t0][3], ql0, ql1, ql2, ql3, kh0, kh1);
                    mma_bf16(s[t1][0], s[t1][1], s[t1][2], s[t1][3], qh0, qh1, qh2, qh3, kh2, kh3);
                    mma_bf16(s[t1][0], s[t1][1], s[t1][2], s[t1][3], qh0, qh1, qh2, qh3, kl2, kl3);
                    mma_bf16(s[t1][0], s[t1][1], s[t1][2], s[t1][3], ql0, ql1, ql2, ql3, kh2, kh3);
                }
            }

            // ---- causal mask on diagonal tile ----
            if (kt == qt) {
                const int r0 = w * 16 + (lane >> 2);
                const int r1 = r0 + 8;
#pragma unroll
                for (int nt = 0; nt < 8; nt++) {
                    int c = nt * 8 + 2 * (lane & 3);
                    if (c     > r0) s[nt][0] = -INFINITY;
                    if (c + 1 > r0) s[nt][1] = -INFINITY;
                    if (c     > r1) s[nt][2] = -INFINITY;
                    if (c + 1 > r1) s[nt][3] = -INFINITY;
                }
            }

            // ---- online softmax (per-warp rows; quad reduce over cols) ----
            float rmax0 = -INFINITY, rmax1 = -INFINITY;
#pragma unroll
            for (int nt = 0; nt < 8; nt++) {
                rmax0 = fmaxf(rmax0, fmaxf(s[nt][0], s[nt][1]));
                rmax1 = fmaxf(rmax1, fmaxf(s[nt][2], s[nt][3]));
            }
            rmax0 = fmaxf(rmax0, __shfl_xor_sync(0xffffffffu, rmax0, 1));
            rmax0 = fmaxf(rmax0, __shfl_xor_sync(0xffffffffu, rmax0, 2));
            rmax1 = fmaxf(rmax1, __shfl_xor_sync(0xffffffffu, rmax1, 1));
            rmax1 = fmaxf(rmax1, __shfl_xor_sync(0xffffffffu, rmax1, 2));

            float mn0 = fmaxf(m0, rmax0), mn1 = fmaxf(m1, rmax1);
            float alpha0 = __expf(m0 - mn0), alpha1 = __expf(m1 - mn1);
            m0 = mn0; m1 = mn1;

            float sum0 = 0.0f, sum1 = 0.0f;
#pragma unroll
            for (int nt = 0; nt < 8; nt++) {
                s[nt][0] = __expf(s[nt][0] - mn0);
                s[nt][1] = __expf(s[nt][1] - mn0);
                s[nt][2] = __expf(s[nt][2] - mn1);
                s[nt][3] = __expf(s[nt][3] - mn1);
                sum0 += s[nt][0] + s[nt][1];
                sum1 += s[nt][2] + s[nt][3];
            }
            sum0 += __shfl_xor_sync(0xffffffffu, sum0, 1);
            sum0 += __shfl_xor_sync(0xffffffffu, sum0, 2);
            sum1 += __shfl_xor_sync(0xffffffffu, sum1, 1);
            sum1 += __shfl_xor_sync(0xffffffffu, sum1, 2);
            l0 = l0 * alpha0 + sum0;
            l1 = l1 * alpha1 + sum1;

#pragma unroll
            for (int t = 0; t < 16; t++) {
                o[t][0] *= alpha0; o[t][1] *= alpha0;
                o[t][2] *= alpha1; o[t][3] *= alpha1;
            }

            // ---- O += P V (P frag built by register remap, split) ----
#pragma unroll
            for (int kk2 = 0; kk2 < 4; kk2++) {
                int t0 = 2 * kk2, t1 = t0 + 1;
                uint32_t ah0, ah1, ah2, ah3, al0, al1, al2, al3;
                split2(s[t0][0], s[t0][1], ah0, al0);
                split2(s[t0][2], s[t0][3], ah1, al1);
                split2(s[t1][0], s[t1][1], ah2, al2);
                split2(s[t1][2], s[t1][3], ah3, al3);
#pragma unroll
                for (int np = 0; np < 8; np++) {
                    uint32_t vh0, vh1, vh2, vh3, vl0, vl1, vl2, vl3;
                    uint32_t voff = v_off + (uint32_t)(kk2 * 16) * AT_ROWB + np * 32;
                    ldsm_x4_t(kb + 2 * AT_TILE + voff, vh0, vh1, vh2, vh3);
                    ldsm_x4_t(kb + 3 * AT_TILE + voff, vl0, vl1, vl2, vl3);
                    int u0 = 2 * np, u1 = u0 + 1;
                    mma_bf16(o[u0][0], o[u0][1], o[u0][2], o[u0][3], ah0, ah1, ah2, ah3, vh0, vh1);
                    mma_bf16(o[u0][0], o[u0][1], o[u0][2], o[u0][3], ah0, ah1, ah2, ah3, vl0, vl1);
                    mma_bf16(o[u0][0], o[u0][1], o[u0][2], o[u0][3], al0, al1, al2, al3, vh0, vh1);
                    mma_bf16(o[u1][0], o[u1][1], o[u1][2], o[u1][3], ah0, ah1, ah2, ah3, vh2, vh3);
                    mma_bf16(o[u1][0], o[u1][1], o[u1][2], o[u1][3], ah0, ah1, ah2, ah3, vl2, vl3);
                    mma_bf16(o[u1][0], o[u1][1], o[u1][2], o[u1][3], al0, al1, al2, al3, vh2, vh3);
                }
            }
        }

        // ---- epilogue: normalize, store fp32 ----
        const float inv0 = 1.0f / l0, inv1 = 1.0f / l1;
        const int gr0 = bbase + qt * 64 + w * 16 + (lane >> 2);
        const int gr1 = gr0 + 8;
#pragma unroll
        for (int nt = 0; nt < 16; nt++) {
            int col = nt * 8 + 2 * (lane & 3);
            *(float2*)(out + (size_t)gr0 * HDIM + col) =
                make_float2(o[nt][0] * inv0, o[nt][1] * inv0);
            *(float2*)(out + (size_t)gr1 * HDIM + col) =
                make_float2(o[nt][2] * inv1, o[nt][3] * inv1);
        }
    }
}

// ---------------------------------------------------------------------------
extern "C" void kernel_launch(void* const* d_in, const int* in_sizes, int n_in,
                              void* d_out, int out_size)
{
    const float* x  = (const float*)d_in[0];
    const float* Wk = (const float*)d_in[1];
    const float* Wq = (const float*)d_in[2];
    const float* Wv = (const float*)d_in[3];
    float* out = (float*)d_out;

    static bool attr_set = false;
    if (!attr_set) {
        cudaFuncSetAttribute(proj_mma_kernel,
                             cudaFuncAttributeMaxDynamicSharedMemorySize, PR_SMEM);
        cudaFuncSetAttribute(attn_mma_kernel,
                             cudaFuncAttributeMaxDynamicSharedMemorySize, AT_SMEM);
        attr_set = true;
    }

    // 1) split weights to bf16 hi/lo
    wsplit_kernel<<<(3 * HDIM * EMB + 255) / 256, 256>>>(Wk, Wq, Wv);

    // 2) Q/K/V projections on tensor cores (bf16-split), outputs pre-split bf16
    proj_mma_kernel<<<dim3(128, 3), 256, PR_SMEM>>>(x);

    // 3) causal flash attention on tensor cores (bf16-split)
    attn_mma_kernel<<<dim3(32, BATCH), 128, AT_SMEM>>>(out);
}